// round 6
// baseline (speedup 1.0000x reference)
#include <cuda_runtime.h>
#include <cuda_fp16.h>
#include <cstdint>

// ===================== problem dims =====================
#define M_DIM 8192      // B*S = 4*2048
#define N_DIM 16384
#define K_DIM 4096

#define BM 128
#define BN 128
#define BK 128                        // s8 elements per K-chunk (128 bytes per row)
#define NCHUNK (K_DIM / BK)           // 32
#define STAGES 4
#define THREADS 256                   // 8 warps: 4m x 2n, warp tile 32x64
#define TILES_M (M_DIM / BM)          // 64
#define TILES_N (N_DIM / BN)          // 128
#define GROUP_M 8                     // raster: m-tiles per group

#define A_SCALE 4096.0f               // s = 2^-12
#define A_SCALE_INV 0.000244140625f

// ===================== scratch (alloc-free) =====================
__device__ int8_t g_Ah[(size_t)M_DIM * K_DIM];  // 32 MB: high bytes of int16 activations
__device__ int8_t g_Al[(size_t)M_DIM * K_DIM];  // 32 MB: low  bytes
__device__ int8_t g_W [(size_t)N_DIM * K_DIM];  // 64 MB: int8 weights (exact)

// ===================== PTX helpers =====================
__device__ __forceinline__ uint32_t smem_to_u32(const void* p) {
    uint32_t a;
    asm("{ .reg .u64 t; cvta.to.shared.u64 t, %1; cvt.u32.u64 %0, t; }" : "=r"(a) : "l"(p));
    return a;
}
__device__ __forceinline__ void cp_async16(uint32_t dst, const void* src) {
    asm volatile("cp.async.cg.shared.global [%0], [%1], 16;" :: "r"(dst), "l"(src));
}
__device__ __forceinline__ void cp_commit() {
    asm volatile("cp.async.commit_group;" ::: "memory");
}
template <int N>
__device__ __forceinline__ void cp_wait() {
    asm volatile("cp.async.wait_group %0;" :: "n"(N) : "memory");
}
__device__ __forceinline__ void ldsm_x4(uint32_t* r, uint32_t addr) {
    asm volatile("ldmatrix.sync.aligned.m8n8.x4.shared.b16 {%0,%1,%2,%3}, [%4];"
                 : "=r"(r[0]), "=r"(r[1]), "=r"(r[2]), "=r"(r[3]) : "r"(addr));
}
// int8 MMA: m16n8k32, s32 accumulate
__device__ __forceinline__ void imma16832(int* d, const uint32_t* a, const uint32_t* b) {
    asm volatile(
        "mma.sync.aligned.m16n8k32.row.col.s32.s8.s8.s32 "
        "{%0,%1,%2,%3}, {%4,%5,%6,%7}, {%8,%9}, {%0,%1,%2,%3};"
        : "+r"(d[0]), "+r"(d[1]), "+r"(d[2]), "+r"(d[3])
        : "r"(a[0]), "r"(a[1]), "r"(a[2]), "r"(a[3]), "r"(b[0]), "r"(b[1]));
}

// SW128 swizzle for 128B rows: 16B chunk index ^= (row & 7)
__device__ __forceinline__ uint32_t swz_row_col(int row, int colbytes) {
    return (uint32_t)(row * 128) + (uint32_t)(colbytes ^ ((row & 7) << 4));
}

// ===================== SMEM layout =====================
#define AH_STAGE_BYTES (BM * 128)             // 16384
#define AL_STAGE_BYTES (BM * 128)             // 16384
#define W_STAGE_BYTES  (BN * 128)             // 16384
#define STAGE_BYTES    (AH_STAGE_BYTES + AL_STAGE_BYTES + W_STAGE_BYTES)  // 49152
#define SMEM_BODY      (STAGES * STAGE_BYTES) // 196608
#define SMEM_TOTAL     (SMEM_BODY + 128)

// ===================== conversion kernels =====================
__device__ __forceinline__ uint32_t pack4(int b0, int b1, int b2, int b3) {
    return (uint32_t)(b0 & 0xff) | ((uint32_t)(b1 & 0xff) << 8) |
           ((uint32_t)(b2 & 0xff) << 16) | ((uint32_t)(b3 & 0xff) << 24);
}

// fp32 -> int16 (fixed scale 2^12) -> split h/l int8 planes. 16 elems/thread.
__global__ void cvtA_kernel(const float4* __restrict__ in) {
    size_t i = (size_t)blockIdx.x * blockDim.x + threadIdx.x;
    int h[16], l[16];
    #pragma unroll
    for (int j = 0; j < 4; j++) {
        float4 v = in[4 * i + j];
        float f[4] = {v.x, v.y, v.z, v.w};
        #pragma unroll
        for (int q = 0; q < 4; q++) {
            float t = rintf(f[q] * A_SCALE);
            t = fminf(fmaxf(t, -32768.0f), 32639.0f);
            int a16 = (int)t;
            int hh = (a16 + 128) >> 8;          // arithmetic shift: floor div
            h[j * 4 + q] = hh;
            l[j * 4 + q] = a16 - (hh << 8);     // in [-128, 127]
        }
    }
    uint4 ph, pl;
    ph.x = pack4(h[0], h[1], h[2], h[3]);   ph.y = pack4(h[4], h[5], h[6], h[7]);
    ph.z = pack4(h[8], h[9], h[10], h[11]); ph.w = pack4(h[12], h[13], h[14], h[15]);
    pl.x = pack4(l[0], l[1], l[2], l[3]);   pl.y = pack4(l[4], l[5], l[6], l[7]);
    pl.z = pack4(l[8], l[9], l[10], l[11]); pl.w = pack4(l[12], l[13], l[14], l[15]);
    reinterpret_cast<uint4*>(g_Ah)[i] = ph;
    reinterpret_cast<uint4*>(g_Al)[i] = pl;
}

// int32 (int8-valued) -> packed s8. 16 elems/thread.
__global__ void cvtW_kernel(const int4* __restrict__ in) {
    size_t i = (size_t)blockIdx.x * blockDim.x + threadIdx.x;
    uint4 p;
    int4 w0 = in[4 * i + 0], w1 = in[4 * i + 1];
    int4 w2 = in[4 * i + 2], w3 = in[4 * i + 3];
    p.x = pack4(w0.x, w0.y, w0.z, w0.w);
    p.y = pack4(w1.x, w1.y, w1.z, w1.w);
    p.z = pack4(w2.x, w2.y, w2.z, w2.w);
    p.w = pack4(w3.x, w3.y, w3.z, w3.w);
    reinterpret_cast<uint4*>(g_W)[i] = p;
}

// ===================== GEMM kernel (IMMA s8, split h/l, 4-stage cp.async) =====================
__global__ void __launch_bounds__(THREADS, 1)
gemm_s8_imma(float* __restrict__ out,
             const float* __restrict__ scale,
             const float* __restrict__ bias) {
    extern __shared__ char smem_raw[];
    char* smem = (char*)(((uintptr_t)smem_raw + 127) & ~(uintptr_t)127);
    const uint32_t sb = smem_to_u32(smem);

    const int tid  = threadIdx.x;
    const int wid  = tid >> 5;
    const int lane = tid & 31;
    const int wm   = wid >> 1;   // 0..3 (m-warp, 32 rows)
    const int wn   = wid & 1;    // 0..1 (n-warp, 64 cols)

    // ---- CTA raster swizzle ----
    const int bid       = blockIdx.x;
    const int per_group = GROUP_M * TILES_N;
    const int g         = bid / per_group;
    const int r_        = bid % per_group;
    const int tile_m    = (g * GROUP_M + (r_ % GROUP_M)) * BM;
    const int tile_n    = (r_ / GROUP_M) * BN;

    const int8_t* ahG = g_Ah + (size_t)tile_m * K_DIM;
    const int8_t* alG = g_Al + (size_t)tile_m * K_DIM;
    const int8_t* wG  = g_W  + (size_t)tile_n * K_DIM;

    // ldmatrix lane maps — byte-offset based, identical structure to validated fp16 kernel
    const int rowA_in16 = ((lane >> 3) & 1) * 8 + (lane & 7);
    const int ksubA     = ((lane >> 4) & 1) * 16;   // bytes
    const int rowB_in16 = ((lane >> 4) & 1) * 8 + (lane & 7);
    const int ksubB     = ((lane >> 3) & 1) * 16;   // bytes

    int acch[2][8][4];
    int accl[2][8][4];
    #pragma unroll
    for (int mt = 0; mt < 2; mt++)
        #pragma unroll
        for (int nt = 0; nt < 8; nt++)
            #pragma unroll
            for (int q = 0; q < 4; q++) { acch[mt][nt][q] = 0; accl[mt][nt][q] = 0; }

    // ---- producer: 3 planes x 128 rows x 8 x16B = 12 cp.async per thread ----
    auto load_stage = [&](int stage, int kc) {
        const uint32_t sAh = sb + stage * STAGE_BYTES;
        const uint32_t sAl = sAh + AH_STAGE_BYTES;
        const uint32_t sW  = sAl + AL_STAGE_BYTES;
        const int kb = kc * BK;   // byte offset along K
        #pragma unroll
        for (int j = 0; j < 4; j++) {
            int idx = tid + j * 256;
            int r = idx >> 3, c = idx & 7;
            cp_async16(sAh + swz_row_col(r, c * 16), ahG + (size_t)r * K_DIM + kb + c * 16);
        }
        #pragma unroll
        for (int j = 0; j < 4; j++) {
            int idx = tid + j * 256;
            int r = idx >> 3, c = idx & 7;
            cp_async16(sAl + swz_row_col(r, c * 16), alG + (size_t)r * K_DIM + kb + c * 16);
        }
        #pragma unroll
        for (int j = 0; j < 4; j++) {
            int idx = tid + j * 256;
            int r = idx >> 3, c = idx & 7;
            cp_async16(sW + swz_row_col(r, c * 16), wG + (size_t)r * K_DIM + kb + c * 16);
        }
    };

    // ---- prologue ----
    #pragma unroll
    for (int s = 0; s < STAGES - 1; s++) {
        load_stage(s, s);
        cp_commit();
    }
    cp_wait<STAGES - 2>();
    __syncthreads();

    // ---- main loop ----
    for (int kc = 0; kc < NCHUNK; kc++) {
        const int kload = kc + STAGES - 1;
        if (kload < NCHUNK) load_stage(kload % STAGES, kload);
        cp_commit();

        const uint32_t sAh = sb + (kc % STAGES) * STAGE_BYTES;
        const uint32_t sAl = sAh + AH_STAGE_BYTES;
        const uint32_t sW  = sAl + AL_STAGE_BYTES;

        #pragma unroll
        for (int ks = 0; ks < 4; ks++) {          // 4 x k32 per BK=128 chunk
            uint32_t ah[2][4], al[2][4];
            #pragma unroll
            for (int mt = 0; mt < 2; mt++) {
                const int row = wm * 32 + mt * 16 + rowA_in16;
                ldsm_x4(ah[mt], sAh + swz_row_col(row, ks * 32 + ksubA));
                ldsm_x4(al[mt], sAl + swz_row_col(row, ks * 32 + ksubA));
            }
            uint32_t b[8][2];
            #pragma unroll
            for (int p = 0; p < 4; p++) {         // each x4 covers two n8-tiles
                const int row = wn * 64 + p * 16 + rowB_in16;
                uint32_t r4[4];
                ldsm_x4(r4, sW + swz_row_col(row, ks * 32 + ksubB));
                b[2 * p][0] = r4[0]; b[2 * p][1] = r4[1];
                b[2 * p + 1][0] = r4[2]; b[2 * p + 1][1] = r4[3];
            }
            #pragma unroll
            for (int mt = 0; mt < 2; mt++)
                #pragma unroll
                for (int nt = 0; nt < 8; nt++) {
                    imma16832(acch[mt][nt], ah[mt], b[nt]);
                    imma16832(accl[mt][nt], al[mt], b[nt]);
                }
        }

        cp_wait<STAGES - 2>();
        __syncthreads();
    }

    // ---- epilogue: out = (256*acc_h + acc_l) * (sw * 2^-12) + bias ----
    const int colbase = tile_n + wn * 64 + (lane & 3) * 2;
    float2 sc[8], bi[8];
    #pragma unroll
    for (int nt = 0; nt < 8; nt++) {
        float2 s2 = *reinterpret_cast<const float2*>(scale + colbase + nt * 8);
        sc[nt].x = s2.x * A_SCALE_INV;
        sc[nt].y = s2.y * A_SCALE_INV;
        bi[nt] = *reinterpret_cast<const float2*>(bias + colbase + nt * 8);
    }

    #pragma unroll
    for (int mt = 0; mt < 2; mt++) {
        const int grow = tile_m + wm * 32 + mt * 16 + (lane >> 2);
        float* o0 = out + (size_t)grow * N_DIM + colbase;
        float* o1 = o0 + (size_t)8 * N_DIM;
        #pragma unroll
        for (int nt = 0; nt < 8; nt++) {
            float c0 = fmaf(256.0f, (float)acch[mt][nt][0], (float)accl[mt][nt][0]);
            float c1 = fmaf(256.0f, (float)acch[mt][nt][1], (float)accl[mt][nt][1]);
            float c2 = fmaf(256.0f, (float)acch[mt][nt][2], (float)accl[mt][nt][2]);
            float c3 = fmaf(256.0f, (float)acch[mt][nt][3], (float)accl[mt][nt][3]);
            float2 v0, v1;
            v0.x = c0 * sc[nt].x + bi[nt].x;
            v0.y = c1 * sc[nt].y + bi[nt].y;
            v1.x = c2 * sc[nt].x + bi[nt].x;
            v1.y = c3 * sc[nt].y + bi[nt].y;
            *reinterpret_cast<float2*>(o0 + nt * 8) = v0;
            *reinterpret_cast<float2*>(o1 + nt * 8) = v1;
        }
    }
}

// ===================== launch =====================
extern "C" void kernel_launch(void* const* d_in, const int* in_sizes, int n_in,
                              void* d_out, int out_size) {
    const float* inp  = (const float*)d_in[0];   // (4, 2048, 4096) f32
    const int*   wgt  = (const int*)d_in[1];     // (16384, 4096) int32 (int8-valued)
    const float* wsc  = (const float*)d_in[2];   // (16384,) f32
    const float* bias = (const float*)d_in[3];   // (16384,) f32
    float* out = (float*)d_out;                  // (4, 2048, 16384) f32

    (void)in_sizes; (void)n_in; (void)out_size;

    // 33,554,432 elems / 16 per thread = 2,097,152 threads
    cvtA_kernel<<<8192, 256>>>(reinterpret_cast<const float4*>(inp));
    // 67,108,864 elems / 16 per thread = 4,194,304 threads
    cvtW_kernel<<<16384, 256>>>(reinterpret_cast<const int4*>(wgt));

    cudaFuncSetAttribute(gemm_s8_imma,
                         cudaFuncAttributeMaxDynamicSharedMemorySize, SMEM_TOTAL);
    gemm_s8_imma<<<TILES_M * TILES_N, THREADS, SMEM_TOTAL>>>(out, wsc, bias);
}

// round 7
// speedup vs baseline: 5.6154x; 5.6154x over previous
#include <cuda_runtime.h>
#include <cuda_fp16.h>
#include <cstdint>

// ===================== problem dims =====================
#define M_DIM 8192      // B*S = 4*2048
#define N_DIM 16384
#define K_DIM 4096

#define BM 128
#define BN 128
#define BK 64                         // halves per K-chunk (128 bytes per row)
#define NCHUNK (K_DIM / BK)           // 64
#define STAGES 3
#define THREADS 128                   // 4 warps, 64x64 warp tiles
#define TILES_M (M_DIM / BM)          // 64
#define TILES_N (N_DIM / BN)          // 128
#define GROUP_M 8                     // raster: m-tiles per group (m fastest within group)

// ===================== scratch (alloc-free) =====================
__device__ __half g_A[(size_t)M_DIM * K_DIM];   // 64 MB fp16 activations
__device__ __half g_B[(size_t)N_DIM * K_DIM];   // 128 MB fp16 weights (exact int8 values)

// ===================== PTX helpers (baseline features only) =====================
__device__ __forceinline__ uint32_t smem_to_u32(const void* p) {
    uint32_t a;
    asm("{ .reg .u64 t; cvta.to.shared.u64 t, %1; cvt.u32.u64 %0, t; }" : "=r"(a) : "l"(p));
    return a;
}
__device__ __forceinline__ void cp_async16(uint32_t dst, const void* src) {
    asm volatile("cp.async.cg.shared.global [%0], [%1], 16;" :: "r"(dst), "l"(src));
}
__device__ __forceinline__ void cp_commit() {
    asm volatile("cp.async.commit_group;" ::: "memory");
}
template <int N>
__device__ __forceinline__ void cp_wait() {
    asm volatile("cp.async.wait_group %0;" :: "n"(N) : "memory");
}
__device__ __forceinline__ void ldsm_x4(uint32_t* r, uint32_t addr) {
    asm volatile("ldmatrix.sync.aligned.m8n8.x4.shared.b16 {%0,%1,%2,%3}, [%4];"
                 : "=r"(r[0]), "=r"(r[1]), "=r"(r[2]), "=r"(r[3]) : "r"(addr));
}
// f16-accumulate HMMA: m16n8k16, D/C in f16 (2 regs) — targets the rt4 (RF-light) path
__device__ __forceinline__ void mma16816_f16(uint32_t* d, const uint32_t* a,
                                             uint32_t b0, uint32_t b1) {
    asm volatile(
        "mma.sync.aligned.m16n8k16.row.col.f16.f16.f16.f16 "
        "{%0,%1}, {%2,%3,%4,%5}, {%6,%7}, {%0,%1};"
        : "+r"(d[0]), "+r"(d[1])
        : "r"(a[0]), "r"(a[1]), "r"(a[2]), "r"(a[3]), "r"(b0), "r"(b1));
}

// SW128 swizzle for 128B rows: 16B chunk index ^= (row & 7)
__device__ __forceinline__ uint32_t swz_row_col(int row, int colbytes) {
    return (uint32_t)(row * 128) + (uint32_t)(colbytes ^ ((row & 7) << 4));
}

// ===================== SMEM layout =====================
#define A_STAGE_BYTES (BM * 128)              // 16384
#define B_STAGE_BYTES (BN * 128)              // 16384
#define STAGE_BYTES   (A_STAGE_BYTES + B_STAGE_BYTES)   // 32768
#define SMEM_BODY     (STAGES * STAGE_BYTES)  // 98304
#define SMEM_TOTAL    (SMEM_BODY + 128)       // manual 128B alignment headroom

// ===================== conversion kernels =====================
struct alignas(16) H8 { __half2 a, b, c, d; };

__global__ void cvtA_kernel(const float4* __restrict__ in) {
    size_t i = (size_t)blockIdx.x * blockDim.x + threadIdx.x;
    float4 v0 = in[2 * i];
    float4 v1 = in[2 * i + 1];
    H8 h;
    h.a = __floats2half2_rn(v0.x, v0.y);
    h.b = __floats2half2_rn(v0.z, v0.w);
    h.c = __floats2half2_rn(v1.x, v1.y);
    h.d = __floats2half2_rn(v1.z, v1.w);
    reinterpret_cast<H8*>(g_A)[i] = h;
}

__global__ void cvtW_kernel(const int4* __restrict__ in) {
    size_t i = (size_t)blockIdx.x * blockDim.x + threadIdx.x;
    int4 v0 = in[2 * i];
    int4 v1 = in[2 * i + 1];
    H8 h;
    h.a = __floats2half2_rn((float)v0.x, (float)v0.y);
    h.b = __floats2half2_rn((float)v0.z, (float)v0.w);
    h.c = __floats2half2_rn((float)v1.x, (float)v1.y);
    h.d = __floats2half2_rn((float)v1.z, (float)v1.w);
    reinterpret_cast<H8*>(g_B)[i] = h;
}

// ===================== GEMM kernel (f16-acc HMMA windows + fp32 master) =====================
__global__ void __launch_bounds__(THREADS, 2)
gemm_f16_hmma(float* __restrict__ out,
              const float* __restrict__ scale,
              const float* __restrict__ bias) {
    extern __shared__ char smem_raw[];
    char* smem = (char*)(((uintptr_t)smem_raw + 127) & ~(uintptr_t)127);
    const uint32_t sb = smem_to_u32(smem);

    const int tid  = threadIdx.x;
    const int wid  = tid >> 5;
    const int lane = tid & 31;
    const int wm   = wid >> 1;   // 0..1  (m-warp, 64 rows)
    const int wn   = wid & 1;    // 0..1  (n-warp, 64 cols)

    // ---- CTA raster swizzle: m fastest within groups of GROUP_M m-tiles ----
    const int bid       = blockIdx.x;
    const int per_group = GROUP_M * TILES_N;           // 1024
    const int g         = bid / per_group;
    const int r_        = bid % per_group;
    const int tile_m    = (g * GROUP_M + (r_ % GROUP_M)) * BM;
    const int tile_n    = (r_ / GROUP_M) * BN;

    const __half* aG = g_A + (size_t)tile_m * K_DIM;
    const __half* bG = g_B + (size_t)tile_n * K_DIM;

    // ldmatrix per-lane row/col-sub mappings (validated round-2/5 logic)
    const int rowA_in16 = ((lane >> 3) & 1) * 8 + (lane & 7);
    const int ksubA     = ((lane >> 4) & 1) * 16;
    const int rowB_in16 = ((lane >> 4) & 1) * 8 + (lane & 7);
    const int ksubB     = ((lane >> 3) & 1) * 16;

    float acc[4][8][4];               // fp32 master accumulator
    uint32_t hacc[4][8][2];           // f16x2 window accumulator (K=128 per window)
    #pragma unroll
    for (int mt = 0; mt < 4; mt++)
        #pragma unroll
        for (int nt = 0; nt < 8; nt++) {
            #pragma unroll
            for (int q = 0; q < 4; q++) acc[mt][nt][q] = 0.0f;
            hacc[mt][nt][0] = 0u; hacc[mt][nt][1] = 0u;
        }

    // ---- producer (all 128 threads): A 128 rows x 8 chunks, B same (16B each) ----
    auto load_stage = [&](int stage, int kc) {
        const uint32_t sA = sb + stage * STAGE_BYTES;
        const uint32_t sB = sA + A_STAGE_BYTES;
        const int kh = kc * BK;   // half offset
        #pragma unroll
        for (int j = 0; j < 8; j++) {
            int idx = tid + j * 128;
            int r = idx >> 3, c = idx & 7;
            cp_async16(sA + swz_row_col(r, c * 16), aG + (size_t)r * K_DIM + kh + c * 8);
        }
        #pragma unroll
        for (int j = 0; j < 8; j++) {
            int idx = tid + j * 128;
            int r = idx >> 3, c = idx & 7;
            cp_async16(sB + swz_row_col(r, c * 16), bG + (size_t)r * K_DIM + kh + c * 8);
        }
    };

    // ---- prologue ----
    #pragma unroll
    for (int s = 0; s < STAGES - 1; s++) {
        load_stage(s, s);
        cp_commit();
    }
    cp_wait<STAGES - 2>();
    __syncthreads();

    // ---- main loop ----
    for (int kc = 0; kc < NCHUNK; kc++) {
        const int kload = kc + STAGES - 1;
        if (kload < NCHUNK) load_stage(kload % STAGES, kload);
        cp_commit();

        const uint32_t sA = sb + (kc % STAGES) * STAGE_BYTES;
        const uint32_t sB = sA + A_STAGE_BYTES;

        #pragma unroll
        for (int ks = 0; ks < 4; ks++) {          // 4 x k16 per BK=64 chunk
            uint32_t a[4][4];
            #pragma unroll
            for (int mt = 0; mt < 4; mt++) {
                const int row = wm * 64 + mt * 16 + rowA_in16;
                ldsm_x4(a[mt], sA + swz_row_col(row, ks * 32 + ksubA));
            }
            #pragma unroll
            for (int p = 0; p < 4; p++) {         // each x4 covers two n8-tiles
                const int row = wn * 64 + p * 16 + rowB_in16;
                uint32_t r4[4];
                ldsm_x4(r4, sB + swz_row_col(row, ks * 32 + ksubB));
                #pragma unroll
                for (int mt = 0; mt < 4; mt++) {
                    mma16816_f16(hacc[mt][2 * p],     a[mt], r4[0], r4[1]);
                    mma16816_f16(hacc[mt][2 * p + 1], a[mt], r4[2], r4[3]);
                }
            }
        }

        // ---- window promotion: every 2 chunks (K=128), fold f16 window into fp32 ----
        if (kc & 1) {
            #pragma unroll
            for (int mt = 0; mt < 4; mt++)
                #pragma unroll
                for (int nt = 0; nt < 8; nt++) {
                    __half2 h0 = *reinterpret_cast<__half2*>(&hacc[mt][nt][0]);
                    __half2 h1 = *reinterpret_cast<__half2*>(&hacc[mt][nt][1]);
                    float2 f0 = __half22float2(h0);
                    float2 f1 = __half22float2(h1);
                    acc[mt][nt][0] += f0.x;
                    acc[mt][nt][1] += f0.y;
                    acc[mt][nt][2] += f1.x;
                    acc[mt][nt][3] += f1.y;
                    hacc[mt][nt][0] = 0u;
                    hacc[mt][nt][1] = 0u;
                }
        }

        cp_wait<STAGES - 2>();
        __syncthreads();
    }

    // ---- epilogue: scale * acc + bias, direct float2 stores ----
    const int colbase = tile_n + wn * 64 + (lane & 3) * 2;
    float2 sc[8], bi[8];
    #pragma unroll
    for (int nt = 0; nt < 8; nt++) {
        sc[nt] = *reinterpret_cast<const float2*>(scale + colbase + nt * 8);
        bi[nt] = *reinterpret_cast<const float2*>(bias  + colbase + nt * 8);
    }

    #pragma unroll
    for (int mt = 0; mt < 4; mt++) {
        const int grow = tile_m + wm * 64 + mt * 16 + (lane >> 2);
        float* o0 = out + (size_t)grow * N_DIM + colbase;
        float* o1 = o0 + (size_t)8 * N_DIM;
        #pragma unroll
        for (int nt = 0; nt < 8; nt++) {
            float2 v0, v1;
            v0.x = acc[mt][nt][0] * sc[nt].x + bi[nt].x;
            v0.y = acc[mt][nt][1] * sc[nt].y + bi[nt].y;
            v1.x = acc[mt][nt][2] * sc[nt].x + bi[nt].x;
            v1.y = acc[mt][nt][3] * sc[nt].y + bi[nt].y;
            *reinterpret_cast<float2*>(o0 + nt * 8) = v0;
            *reinterpret_cast<float2*>(o1 + nt * 8) = v1;
        }
    }
}

// ===================== launch =====================
extern "C" void kernel_launch(void* const* d_in, const int* in_sizes, int n_in,
                              void* d_out, int out_size) {
    const float* inp  = (const float*)d_in[0];   // (4, 2048, 4096) f32
    const int*   wgt  = (const int*)d_in[1];     // (16384, 4096) int32 (int8-valued)
    const float* wsc  = (const float*)d_in[2];   // (16384,) f32
    const float* bias = (const float*)d_in[3];   // (16384,) f32
    float* out = (float*)d_out;                  // (4, 2048, 16384) f32

    (void)in_sizes; (void)n_in; (void)out_size;

    cvtA_kernel<<<16384, 256>>>(reinterpret_cast<const float4*>(inp));
    cvtW_kernel<<<32768, 256>>>(reinterpret_cast<const int4*>(wgt));

    cudaFuncSetAttribute(gemm_f16_hmma,
                         cudaFuncAttributeMaxDynamicSharedMemorySize, SMEM_TOTAL);
    gemm_f16_hmma<<<TILES_M * TILES_N, THREADS, SMEM_TOTAL>>>(out, wsc, bias);
}

// round 8
// speedup vs baseline: 6.7693x; 1.2055x over previous
#include <cuda_runtime.h>
#include <cuda_fp16.h>
#include <cstdint>

// ===================== problem dims =====================
#define M_DIM 8192      // B*S = 4*2048
#define N_DIM 16384
#define K_DIM 4096

#define BM 128
#define BN 128
#define BK 64                         // halves per K-chunk (128 bytes per row)
#define NCHUNK (K_DIM / BK)           // 64
#define STAGES 3
#define THREADS 128                   // 4 warps, 64x64 warp tiles
#define TILES_M (M_DIM / BM)          // 64
#define TILES_N (N_DIM / BN)          // 128
#define GROUP_M 16                    // raster: m-tiles per group (4 exact passes over B)

// ===================== scratch (alloc-free) =====================
__device__ __half g_A[(size_t)M_DIM * K_DIM];   // 64 MB fp16 activations
__device__ __half g_B[(size_t)N_DIM * K_DIM];   // 128 MB fp16 weights (exact int8 values)

// ===================== PTX helpers (baseline features only) =====================
__device__ __forceinline__ uint32_t smem_to_u32(const void* p) {
    uint32_t a;
    asm("{ .reg .u64 t; cvta.to.shared.u64 t, %1; cvt.u32.u64 %0, t; }" : "=r"(a) : "l"(p));
    return a;
}
__device__ __forceinline__ void cp_async16(uint32_t dst, const void* src) {
    asm volatile("cp.async.cg.shared.global [%0], [%1], 16;" :: "r"(dst), "l"(src));
}
__device__ __forceinline__ void cp_commit() {
    asm volatile("cp.async.commit_group;" ::: "memory");
}
template <int N>
__device__ __forceinline__ void cp_wait() {
    asm volatile("cp.async.wait_group %0;" :: "n"(N) : "memory");
}
__device__ __forceinline__ void ldsm_x4(uint32_t* r, uint32_t addr) {
    asm volatile("ldmatrix.sync.aligned.m8n8.x4.shared.b16 {%0,%1,%2,%3}, [%4];"
                 : "=r"(r[0]), "=r"(r[1]), "=r"(r[2]), "=r"(r[3]) : "r"(addr));
}
__device__ __forceinline__ void mma16816(float* d, const uint32_t* a, const uint32_t* b) {
    asm volatile(
        "mma.sync.aligned.m16n8k16.row.col.f32.f16.f16.f32 "
        "{%0,%1,%2,%3}, {%4,%5,%6,%7}, {%8,%9}, {%0,%1,%2,%3};"
        : "+f"(d[0]), "+f"(d[1]), "+f"(d[2]), "+f"(d[3])
        : "r"(a[0]), "r"(a[1]), "r"(a[2]), "r"(a[3]), "r"(b[0]), "r"(b[1]));
}

// SW128 swizzle for 128B rows: 16B chunk index ^= (row & 7)
__device__ __forceinline__ uint32_t swz_row_col(int row, int colbytes) {
    return (uint32_t)(row * 128) + (uint32_t)(colbytes ^ ((row & 7) << 4));
}

// ===================== SMEM layout =====================
#define A_STAGE_BYTES (BM * 128)              // 16384
#define B_STAGE_BYTES (BN * 128)              // 16384
#define STAGE_BYTES   (A_STAGE_BYTES + B_STAGE_BYTES)   // 32768
#define SMEM_BODY     (STAGES * STAGE_BYTES)  // 98304
#define SMEM_TOTAL    (SMEM_BODY + 128)       // manual 128B alignment headroom

// ===================== conversion kernels =====================
struct alignas(16) H8 { __half2 a, b, c, d; };

__global__ void cvtA_kernel(const float4* __restrict__ in) {
    size_t i = (size_t)blockIdx.x * blockDim.x + threadIdx.x;
    float4 v0 = in[2 * i];
    float4 v1 = in[2 * i + 1];
    H8 h;
    h.a = __floats2half2_rn(v0.x, v0.y);
    h.b = __floats2half2_rn(v0.z, v0.w);
    h.c = __floats2half2_rn(v1.x, v1.y);
    h.d = __floats2half2_rn(v1.z, v1.w);
    reinterpret_cast<H8*>(g_A)[i] = h;
}

__global__ void cvtW_kernel(const int4* __restrict__ in) {
    size_t i = (size_t)blockIdx.x * blockDim.x + threadIdx.x;
    int4 v0 = in[2 * i];
    int4 v1 = in[2 * i + 1];
    H8 h;
    h.a = __floats2half2_rn((float)v0.x, (float)v0.y);
    h.b = __floats2half2_rn((float)v0.z, (float)v0.w);
    h.c = __floats2half2_rn((float)v1.x, (float)v1.y);
    h.d = __floats2half2_rn((float)v1.z, (float)v1.w);
    reinterpret_cast<H8*>(g_B)[i] = h;
}

// ===================== GEMM kernel (HMMA f32-acc, interleaved cp.async, frag ping-pong) ====
__global__ void __launch_bounds__(THREADS, 2)
gemm_f16_hmma(float* __restrict__ out,
              const float* __restrict__ scale,
              const float* __restrict__ bias) {
    extern __shared__ char smem_raw[];
    char* smem = (char*)(((uintptr_t)smem_raw + 127) & ~(uintptr_t)127);
    const uint32_t sb = smem_to_u32(smem);

    const int tid  = threadIdx.x;
    const int wid  = tid >> 5;
    const int lane = tid & 31;
    const int wm   = wid >> 1;   // 0..1  (m-warp, 64 rows)
    const int wn   = wid & 1;    // 0..1  (n-warp, 64 cols)

    // ---- CTA raster swizzle: m fastest within groups of GROUP_M m-tiles ----
    const int bid       = blockIdx.x;
    const int per_group = GROUP_M * TILES_N;           // 2048
    const int g         = bid / per_group;
    const int r_        = bid % per_group;
    const int tile_m    = (g * GROUP_M + (r_ % GROUP_M)) * BM;
    const int tile_n    = (r_ / GROUP_M) * BN;

    const __half* aG = g_A + (size_t)tile_m * K_DIM;
    const __half* bG = g_B + (size_t)tile_n * K_DIM;

    // ldmatrix per-lane row/col-sub mappings (validated round-2/5 logic)
    const int rowA_in16 = ((lane >> 3) & 1) * 8 + (lane & 7);
    const int ksubA     = ((lane >> 4) & 1) * 16;
    const int rowB_in16 = ((lane >> 4) & 1) * 8 + (lane & 7);
    const int ksubB     = ((lane >> 3) & 1) * 16;

    // precomputed per-thread cp.async row/col (idx = tid + j*128 ; r = idx>>3, c = idx&7)
    // j-th slice handled inside the ks loop.
    const int cp_r0 = tid >> 3;            // rows advance by 16 per j
    const int cp_c  = tid & 7;

    float acc[4][8][4];
    #pragma unroll
    for (int mt = 0; mt < 4; mt++)
        #pragma unroll
        for (int nt = 0; nt < 8; nt++)
            #pragma unroll
            for (int q = 0; q < 4; q++) acc[mt][nt][q] = 0.0f;

    // ---- full-chunk producer (prologue only) ----
    auto load_stage_full = [&](int stage, int kc) {
        const uint32_t sA = sb + stage * STAGE_BYTES;
        const uint32_t sB = sA + A_STAGE_BYTES;
        const int kh = kc * BK;
        #pragma unroll
        for (int j = 0; j < 8; j++) {
            int r = cp_r0 + j * 16;
            cp_async16(sA + swz_row_col(r, cp_c * 16), aG + (size_t)r * K_DIM + kh + cp_c * 8);
        }
        #pragma unroll
        for (int j = 0; j < 8; j++) {
            int r = cp_r0 + j * 16;
            cp_async16(sB + swz_row_col(r, cp_c * 16), bG + (size_t)r * K_DIM + kh + cp_c * 8);
        }
    };

    // ---- fragment loader for one k16 step ----
    auto load_frags = [&](uint32_t sA, uint32_t sB, int ks,
                          uint32_t a[4][4], uint32_t b[8][2]) {
        #pragma unroll
        for (int mt = 0; mt < 4; mt++) {
            const int row = wm * 64 + mt * 16 + rowA_in16;
            ldsm_x4(a[mt], sA + swz_row_col(row, ks * 32 + ksubA));
        }
        #pragma unroll
        for (int p = 0; p < 4; p++) {
            const int row = wn * 64 + p * 16 + rowB_in16;
            uint32_t r4[4];
            ldsm_x4(r4, sB + swz_row_col(row, ks * 32 + ksubB));
            b[2 * p][0] = r4[0]; b[2 * p][1] = r4[1];
            b[2 * p + 1][0] = r4[2]; b[2 * p + 1][1] = r4[3];
        }
    };

    // ---- prologue ----
    #pragma unroll
    for (int s = 0; s < STAGES - 1; s++) {
        load_stage_full(s, s);
        cp_commit();
    }
    cp_wait<STAGES - 2>();
    __syncthreads();

    // ---- main loop: interleaved loads + register ping-pong fragments ----
    for (int kc = 0; kc < NCHUNK; kc++) {
        const int kload   = kc + STAGES - 1;
        const bool doLoad = (kload < NCHUNK);
        const int  lstage = kload % STAGES;
        const uint32_t lA = sb + lstage * STAGE_BYTES;
        const uint32_t lB = lA + A_STAGE_BYTES;
        const int khl     = kload * BK;

        const uint32_t sA = sb + (kc % STAGES) * STAGE_BYTES;
        const uint32_t sB = sA + A_STAGE_BYTES;

        uint32_t afrag[2][4][4];
        uint32_t bfrag[2][8][2];
        load_frags(sA, sB, 0, afrag[0], bfrag[0]);

        #pragma unroll
        for (int ks = 0; ks < 4; ks++) {
            const int cur = ks & 1;
            // prefetch next k16 fragments before issuing MMAs
            if (ks < 3) load_frags(sA, sB, ks + 1, afrag[cur ^ 1], bfrag[cur ^ 1]);

            // interleave 4 cp.async (2 A-slices + 2 B-slices) for the prefetch chunk
            if (doLoad) {
                #pragma unroll
                for (int q = 0; q < 2; q++) {
                    int r = cp_r0 + (ks * 2 + q) * 16;
                    cp_async16(lA + swz_row_col(r, cp_c * 16),
                               aG + (size_t)r * K_DIM + khl + cp_c * 8);
                    cp_async16(lB + swz_row_col(r, cp_c * 16),
                               bG + (size_t)r * K_DIM + khl + cp_c * 8);
                }
            }

            #pragma unroll
            for (int mt = 0; mt < 4; mt++)
                #pragma unroll
                for (int nt = 0; nt < 8; nt++)
                    mma16816(acc[mt][nt], afrag[cur][mt], bfrag[cur][nt]);
        }
        cp_commit();

        cp_wait<STAGES - 2>();
        __syncthreads();
    }

    // ---- epilogue: scale * acc + bias, direct float2 stores ----
    const int colbase = tile_n + wn * 64 + (lane & 3) * 2;
    float2 sc[8], bi[8];
    #pragma unroll
    for (int nt = 0; nt < 8; nt++) {
        sc[nt] = *reinterpret_cast<const float2*>(scale + colbase + nt * 8);
        bi[nt] = *reinterpret_cast<const float2*>(bias  + colbase + nt * 8);
    }

    #pragma unroll
    for (int mt = 0; mt < 4; mt++) {
        const int grow = tile_m + wm * 64 + mt * 16 + (lane >> 2);
        float* o0 = out + (size_t)grow * N_DIM + colbase;
        float* o1 = o0 + (size_t)8 * N_DIM;
        #pragma unroll
        for (int nt = 0; nt < 8; nt++) {
            float2 v0, v1;
            v0.x = acc[mt][nt][0] * sc[nt].x + bi[nt].x;
            v0.y = acc[mt][nt][1] * sc[nt].y + bi[nt].y;
            v1.x = acc[mt][nt][2] * sc[nt].x + bi[nt].x;
            v1.y = acc[mt][nt][3] * sc[nt].y + bi[nt].y;
            *reinterpret_cast<float2*>(o0 + nt * 8) = v0;
            *reinterpret_cast<float2*>(o1 + nt * 8) = v1;
        }
    }
}

// ===================== launch =====================
extern "C" void kernel_launch(void* const* d_in, const int* in_sizes, int n_in,
                              void* d_out, int out_size) {
    const float* inp  = (const float*)d_in[0];   // (4, 2048, 4096) f32
    const int*   wgt  = (const int*)d_in[1];     // (16384, 4096) int32 (int8-valued)
    const float* wsc  = (const float*)d_in[2];   // (16384,) f32
    const float* bias = (const float*)d_in[3];   // (16384,) f32
    float* out = (float*)d_out;                  // (4, 2048, 16384) f32

    (void)in_sizes; (void)n_in; (void)out_size;

    cvtA_kernel<<<16384, 256>>>(reinterpret_cast<const float4*>(inp));
    cvtW_kernel<<<32768, 256>>>(reinterpret_cast<const int4*>(wgt));

    cudaFuncSetAttribute(gemm_f16_hmma,
                         cudaFuncAttributeMaxDynamicSharedMemorySize, SMEM_TOTAL);
    gemm_f16_hmma<<<TILES_M * TILES_N, THREADS, SMEM_TOTAL>>>(out, wsc, bias);
}

// round 9
// speedup vs baseline: 6.8715x; 1.0151x over previous
#include <cuda_runtime.h>
#include <cuda_fp16.h>
#include <cstdint>

// ===================== problem dims =====================
#define M_DIM 8192      // B*S = 4*2048
#define N_DIM 16384
#define K_DIM 4096

#define BM 128
#define BN 128
#define BK 64                         // halves per K-chunk (128 bytes per row)
#define NCHUNK (K_DIM / BK)           // 64
#define STAGES 3
#define THREADS 128                   // 4 warps, 64x64 warp tiles
#define TILES_M (M_DIM / BM)          // 64
#define TILES_N (N_DIM / BN)          // 128
#define GROUP_M 32                    // raster: m-tiles per group (2 exact passes over B)

// ===================== scratch (alloc-free) =====================
__device__ __half g_A[(size_t)M_DIM * K_DIM];   // 64 MB fp16 activations
__device__ __half g_B[(size_t)N_DIM * K_DIM];   // 128 MB fp16 weights (exact int8 values)

// ===================== PTX helpers (baseline features only) =====================
__device__ __forceinline__ uint32_t smem_to_u32(const void* p) {
    uint32_t a;
    asm("{ .reg .u64 t; cvta.to.shared.u64 t, %1; cvt.u32.u64 %0, t; }" : "=r"(a) : "l"(p));
    return a;
}
__device__ __forceinline__ void cp_async16(uint32_t dst, const void* src) {
    asm volatile("cp.async.cg.shared.global [%0], [%1], 16;" :: "r"(dst), "l"(src));
}
__device__ __forceinline__ void cp_commit() {
    asm volatile("cp.async.commit_group;" ::: "memory");
}
template <int N>
__device__ __forceinline__ void cp_wait() {
    asm volatile("cp.async.wait_group %0;" :: "n"(N) : "memory");
}
__device__ __forceinline__ void ldsm_x4(uint32_t* r, uint32_t addr) {
    asm volatile("ldmatrix.sync.aligned.m8n8.x4.shared.b16 {%0,%1,%2,%3}, [%4];"
                 : "=r"(r[0]), "=r"(r[1]), "=r"(r[2]), "=r"(r[3]) : "r"(addr));
}
__device__ __forceinline__ void mma16816(float* d, const uint32_t* a, const uint32_t* b) {
    asm volatile(
        "mma.sync.aligned.m16n8k16.row.col.f32.f16.f16.f32 "
        "{%0,%1,%2,%3}, {%4,%5,%6,%7}, {%8,%9}, {%0,%1,%2,%3};"
        : "+f"(d[0]), "+f"(d[1]), "+f"(d[2]), "+f"(d[3])
        : "r"(a[0]), "r"(a[1]), "r"(a[2]), "r"(a[3]), "r"(b[0]), "r"(b[1]));
}

// SW128 swizzle for 128B rows: 16B chunk index ^= (row & 7)
__device__ __forceinline__ uint32_t swz_row_col(int row, int colbytes) {
    return (uint32_t)(row * 128) + (uint32_t)(colbytes ^ ((row & 7) << 4));
}

// ===================== SMEM layout =====================
#define A_STAGE_BYTES (BM * 128)              // 16384
#define B_STAGE_BYTES (BN * 128)              // 16384
#define STAGE_BYTES   (A_STAGE_BYTES + B_STAGE_BYTES)   // 32768
#define SMEM_BODY     (STAGES * STAGE_BYTES)  // 98304
#define SMEM_TOTAL    (SMEM_BODY + 128)       // manual 128B alignment headroom

// ===================== conversion kernels =====================
struct alignas(16) H8 { __half2 a, b, c, d; };

__global__ void cvtA_kernel(const float4* __restrict__ in) {
    size_t i = (size_t)blockIdx.x * blockDim.x + threadIdx.x;
    float4 v0 = in[2 * i];
    float4 v1 = in[2 * i + 1];
    H8 h;
    h.a = __floats2half2_rn(v0.x, v0.y);
    h.b = __floats2half2_rn(v0.z, v0.w);
    h.c = __floats2half2_rn(v1.x, v1.y);
    h.d = __floats2half2_rn(v1.z, v1.w);
    reinterpret_cast<H8*>(g_A)[i] = h;
}

__global__ void cvtW_kernel(const int4* __restrict__ in) {
    size_t i = (size_t)blockIdx.x * blockDim.x + threadIdx.x;
    int4 v0 = in[2 * i];
    int4 v1 = in[2 * i + 1];
    H8 h;
    h.a = __floats2half2_rn((float)v0.x, (float)v0.y);
    h.b = __floats2half2_rn((float)v0.z, (float)v0.w);
    h.c = __floats2half2_rn((float)v1.x, (float)v1.y);
    h.d = __floats2half2_rn((float)v1.z, (float)v1.w);
    reinterpret_cast<H8*>(g_B)[i] = h;
}

// ===================== GEMM kernel (HMMA f32-acc, interleaved cp.async, frag ping-pong) ====
__global__ void __launch_bounds__(THREADS, 2)
gemm_f16_hmma(float* __restrict__ out,
              const float* __restrict__ scale,
              const float* __restrict__ bias) {
    extern __shared__ char smem_raw[];
    char* smem = (char*)(((uintptr_t)smem_raw + 127) & ~(uintptr_t)127);
    const uint32_t sb = smem_to_u32(smem);

    const int tid  = threadIdx.x;
    const int wid  = tid >> 5;
    const int lane = tid & 31;
    const int wm   = wid >> 1;   // 0..1  (m-warp, 64 rows)
    const int wn   = wid & 1;    // 0..1  (n-warp, 64 cols)

    // ---- CTA raster swizzle: m fastest within groups of GROUP_M m-tiles ----
    const int bid       = blockIdx.x;
    const int per_group = GROUP_M * TILES_N;           // 4096
    const int g         = bid / per_group;
    const int r_        = bid % per_group;
    const int tile_m    = (g * GROUP_M + (r_ % GROUP_M)) * BM;
    const int tile_n    = (r_ / GROUP_M) * BN;

    const __half* aG = g_A + (size_t)tile_m * K_DIM;
    const __half* bG = g_B + (size_t)tile_n * K_DIM;

    // ldmatrix per-lane row/col-sub mappings (validated round-2/5 logic)
    const int rowA_in16 = ((lane >> 3) & 1) * 8 + (lane & 7);
    const int ksubA     = ((lane >> 4) & 1) * 16;
    const int rowB_in16 = ((lane >> 4) & 1) * 8 + (lane & 7);
    const int ksubB     = ((lane >> 3) & 1) * 16;

    // per-thread cp.async coordinates (idx = tid + j*128 ; r = idx>>3, c = idx&7)
    const int cp_r0 = tid >> 3;            // rows advance by 16 per j
    const int cp_c  = tid & 7;

    float acc[4][8][4];
    #pragma unroll
    for (int mt = 0; mt < 4; mt++)
        #pragma unroll
        for (int nt = 0; nt < 8; nt++)
            #pragma unroll
            for (int q = 0; q < 4; q++) acc[mt][nt][q] = 0.0f;

    // ---- full-chunk producer (prologue only) ----
    auto load_stage_full = [&](int stage, int kc) {
        const uint32_t sA = sb + stage * STAGE_BYTES;
        const uint32_t sB = sA + A_STAGE_BYTES;
        const int kh = kc * BK;
        #pragma unroll
        for (int j = 0; j < 8; j++) {
            int r = cp_r0 + j * 16;
            cp_async16(sA + swz_row_col(r, cp_c * 16), aG + (size_t)r * K_DIM + kh + cp_c * 8);
        }
        #pragma unroll
        for (int j = 0; j < 8; j++) {
            int r = cp_r0 + j * 16;
            cp_async16(sB + swz_row_col(r, cp_c * 16), bG + (size_t)r * K_DIM + kh + cp_c * 8);
        }
    };

    // ---- fragment loader for one k16 step ----
    auto load_frags = [&](uint32_t sA, uint32_t sB, int ks,
                          uint32_t a[4][4], uint32_t b[8][2]) {
        #pragma unroll
        for (int mt = 0; mt < 4; mt++) {
            const int row = wm * 64 + mt * 16 + rowA_in16;
            ldsm_x4(a[mt], sA + swz_row_col(row, ks * 32 + ksubA));
        }
        #pragma unroll
        for (int p = 0; p < 4; p++) {
            const int row = wn * 64 + p * 16 + rowB_in16;
            uint32_t r4[4];
            ldsm_x4(r4, sB + swz_row_col(row, ks * 32 + ksubB));
            b[2 * p][0] = r4[0]; b[2 * p][1] = r4[1];
            b[2 * p + 1][0] = r4[2]; b[2 * p + 1][1] = r4[3];
        }
    };

    // ---- prologue ----
    #pragma unroll
    for (int s = 0; s < STAGES - 1; s++) {
        load_stage_full(s, s);
        cp_commit();
    }
    cp_wait<STAGES - 2>();
    __syncthreads();

    // ---- main loop: rotating stage counters (no modulo), interleaved loads, frag ping-pong
    int cstage = 0;                        // stage being consumed
    int lstage = STAGES - 1;               // stage being filled
    for (int kc = 0; kc < NCHUNK; kc++) {
        const int  kload  = kc + STAGES - 1;
        const bool doLoad = (kload < NCHUNK);
        const uint32_t lA = sb + lstage * STAGE_BYTES;
        const uint32_t lB = lA + A_STAGE_BYTES;
        const int  khl    = kload * BK;

        const uint32_t sA = sb + cstage * STAGE_BYTES;
        const uint32_t sB = sA + A_STAGE_BYTES;

        uint32_t afrag[2][4][4];
        uint32_t bfrag[2][8][2];
        load_frags(sA, sB, 0, afrag[0], bfrag[0]);

        #pragma unroll
        for (int ks = 0; ks < 4; ks++) {
            const int cur = ks & 1;
            // prefetch next k16 fragments before issuing MMAs
            if (ks < 3) load_frags(sA, sB, ks + 1, afrag[cur ^ 1], bfrag[cur ^ 1]);

            // interleave 4 cp.async (2 A-slices + 2 B-slices) for the prefetch chunk
            if (doLoad) {
                #pragma unroll
                for (int q = 0; q < 2; q++) {
                    int r = cp_r0 + (ks * 2 + q) * 16;
                    cp_async16(lA + swz_row_col(r, cp_c * 16),
                               aG + (size_t)r * K_DIM + khl + cp_c * 8);
                    cp_async16(lB + swz_row_col(r, cp_c * 16),
                               bG + (size_t)r * K_DIM + khl + cp_c * 8);
                }
            }

            #pragma unroll
            for (int mt = 0; mt < 4; mt++)
                #pragma unroll
                for (int nt = 0; nt < 8; nt++)
                    mma16816(acc[mt][nt], afrag[cur][mt], bfrag[cur][nt]);
        }
        cp_commit();

        cp_wait<STAGES - 2>();
        __syncthreads();

        if (++cstage == STAGES) cstage = 0;
        if (++lstage == STAGES) lstage = 0;
    }

    // ---- epilogue: scale * acc + bias, direct float2 stores ----
    const int colbase = tile_n + wn * 64 + (lane & 3) * 2;
    float2 sc[8], bi[8];
    #pragma unroll
    for (int nt = 0; nt < 8; nt++) {
        sc[nt] = *reinterpret_cast<const float2*>(scale + colbase + nt * 8);
        bi[nt] = *reinterpret_cast<const float2*>(bias  + colbase + nt * 8);
    }

    #pragma unroll
    for (int mt = 0; mt < 4; mt++) {
        const int grow = tile_m + wm * 64 + mt * 16 + (lane >> 2);
        float* o0 = out + (size_t)grow * N_DIM + colbase;
        float* o1 = o0 + (size_t)8 * N_DIM;
        #pragma unroll
        for (int nt = 0; nt < 8; nt++) {
            float2 v0, v1;
            v0.x = acc[mt][nt][0] * sc[nt].x + bi[nt].x;
            v0.y = acc[mt][nt][1] * sc[nt].y + bi[nt].y;
            v1.x = acc[mt][nt][2] * sc[nt].x + bi[nt].x;
            v1.y = acc[mt][nt][3] * sc[nt].y + bi[nt].y;
            *reinterpret_cast<float2*>(o0 + nt * 8) = v0;
            *reinterpret_cast<float2*>(o1 + nt * 8) = v1;
        }
    }
}

// ===================== launch =====================
extern "C" void kernel_launch(void* const* d_in, const int* in_sizes, int n_in,
                              void* d_out, int out_size) {
    const float* inp  = (const float*)d_in[0];   // (4, 2048, 4096) f32
    const int*   wgt  = (const int*)d_in[1];     // (16384, 4096) int32 (int8-valued)
    const float* wsc  = (const float*)d_in[2];   // (16384,) f32
    const float* bias = (const float*)d_in[3];   // (16384,) f32
    float* out = (float*)d_out;                  // (4, 2048, 16384) f32

    (void)in_sizes; (void)n_in; (void)out_size;

    cvtA_kernel<<<16384, 256>>>(reinterpret_cast<const float4*>(inp));
    cvtW_kernel<<<32768, 256>>>(reinterpret_cast<const int4*>(wgt));

    cudaFuncSetAttribute(gemm_f16_hmma,
                         cudaFuncAttributeMaxDynamicSharedMemorySize, SMEM_TOTAL);
    gemm_f16_hmma<<<TILES_M * TILES_N, THREADS, SMEM_TOTAL>>>(out, wsc, bias);
}